// round 11
// baseline (speedup 1.0000x reference)
#include <cuda_runtime.h>
#include <cuda_bf16.h>
#include <cuda_fp16.h>

#define FHh 96
#define FWw 320
#define NPIX (FHh*FWw)

__device__ __half g_imgH[NPIX * 64];          // [pixel][64ch] fp16, 128B rows
__device__ unsigned g_Bh[3 * 2304];           // Wl pairs, rows e/2 x stride 72
__device__ unsigned g_Bl[3 * 2304];
__device__ unsigned g_W9h[3 * 768];           // W9 pairs, rows e/2 x stride 24
__device__ unsigned g_W9l[3 * 768];

typedef unsigned long long ull;

static __device__ __forceinline__ ull pk2(float x, float y) {
    ull r; asm("mov.b64 %0,{%1,%2};" : "=l"(r) : "f"(x), "f"(y)); return r;
}
static __device__ __forceinline__ float2 upk2(ull v) {
    float2 r; asm("mov.b64 {%0,%1},%2;" : "=f"(r.x), "=f"(r.y) : "l"(v)); return r;
}
static __device__ __forceinline__ void fma2(ull &d, ull a, ull b) {
    asm("fma.rn.f32x2 %0,%1,%2,%0;" : "+l"(d) : "l"(a), "l"(b));
}
static __device__ __forceinline__ unsigned pkbf(float lo, float hi) {
    unsigned r; asm("cvt.rn.bf16x2.f32 %0, %1, %2;" : "=r"(r) : "f"(hi), "f"(lo)); return r;
}
static __device__ __forceinline__ void mma16816(float &d0, float &d1, float &d2, float &d3,
                                                unsigned a0, unsigned a2,
                                                unsigned b0, unsigned b1) {
    asm volatile("mma.sync.aligned.m16n8k16.row.col.f32.bf16.bf16.f32 "
                 "{%0,%1,%2,%3},{%4,%5,%6,%7},{%8,%9},{%0,%1,%2,%3};"
                 : "+f"(d0), "+f"(d1), "+f"(d2), "+f"(d3)
                 : "r"(a0), "r"(0u), "r"(a2), "r"(0u), "r"(b0), "r"(b1));
}
static __device__ __forceinline__ float bfr(float x) {
    return __bfloat162float(__float2bfloat16(x));
}

// ---------- prologue: transpose img -> fp16 rows (blocks 0-959) + weight prep ----
__global__ void prologue_kernel(const float* __restrict__ src,
                                const float* __restrict__ Wl,
                                const float* __restrict__ Woff,
                                const float* __restrict__ Ww) {
    int b = blockIdx.x, tid = threadIdx.x;
    if (b < 960) {
        __shared__ float t[64][33];
        int p0 = b * 32;
        int tx = tid & 31, ty = tid >> 5;
        #pragma unroll
        for (int r = 0; r < 64; r += 8)
            t[ty + r][tx] = src[(size_t)(ty + r) * NPIX + p0 + tx];
        __syncthreads();
        #pragma unroll
        for (int i = 0; i < 4; i++) {
            int idx = tid + i * 256;            // 0..1023
            int px = idx >> 5, e2 = idx & 31;
            __half2 hv = __floats2half2_rn(t[2*e2][px], t[2*e2+1][px]);
            *(__half2*)&g_imgH[(size_t)(p0 + px) * 64 + 2*e2] = hv;
        }
    } else {
        int it = b - 960;
        for (int idx = tid; idx < 2048; idx += 256) {
            int e2 = idx >> 6, j = idx & 63;
            float a = Wl[it*4096 + (2*e2)*64 + j];
            float bb = Wl[it*4096 + (2*e2+1)*64 + j];
            float ha = bfr(a), hb = bfr(bb);
            g_Bh[it*2304 + e2*72 + j] = pkbf(ha, hb);
            g_Bl[it*2304 + e2*72 + j] = pkbf(a - ha, bb - hb);
        }
        for (int idx = tid; idx < 512; idx += 256) {
            int e2 = idx >> 4, j = idx & 15;
            float a = 0.f, bb = 0.f;
            if (j < 6)      { a = Woff[it*384 + (2*e2)*6 + j];   bb = Woff[it*384 + (2*e2+1)*6 + j]; }
            else if (j < 9) { a = Ww[it*192 + (2*e2)*3 + (j-6)]; bb = Ww[it*192 + (2*e2+1)*3 + (j-6)]; }
            float ha = bfr(a), hb = bfr(bb);
            g_W9h[it*768 + e2*24 + j] = pkbf(ha, hb);
            g_W9l[it*768 + e2*24 + j] = pkbf(a - ha, bb - hb);
        }
    }
}

// ---- fp16 corner gather: lane cc holds channels [8cc, 8cc+8) -> 1 line/pixel ----
static __device__ __forceinline__ void gather8h(int cx, int cy, float wgt,
                                                ull A[4], int cc) {
    if ((unsigned)cx < (unsigned)FWw && (unsigned)cy < (unsigned)FHh) {
        const uint4* p = (const uint4*)&g_imgH[(size_t)(cy * FWw + cx) * 64 + cc * 8];
        uint4 q = *p;
        ull w2 = pk2(wgt, wgt);
        float2 f0 = __half22float2(*(__half2*)&q.x);
        float2 f1 = __half22float2(*(__half2*)&q.y);
        float2 f2 = __half22float2(*(__half2*)&q.z);
        float2 f3 = __half22float2(*(__half2*)&q.w);
        fma2(A[0], w2, pk2(f0.x, f0.y));
        fma2(A[1], w2, pk2(f1.x, f1.y));
        fma2(A[2], w2, pk2(f2.x, f2.y));
        fma2(A[3], w2, pk2(f3.x, f3.y));
    }
}

// Resident: warp = z-column (8 voxels), lane = v*4+c.
// PERMUTED channels: bv[4m+{0,1,2,3}] = ch {16m+2c, +1, 16m+8+2c, +1}.
__global__ __launch_bounds__(256, 3) void bev_kernel(
    const float* __restrict__ velo,  const float* __restrict__ intr,
    const float* __restrict__ bev_emb,
    const float* __restrict__ boff,  const float* __restrict__ soff,
    const float* __restrict__ bw,    const float* __restrict__ bl,
    const float* __restrict__ lng,   const float* __restrict__ lnb,
    float* __restrict__ out)
{
    __shared__ unsigned s_Bh[32 * 72];
    __shared__ unsigned s_Bl[32 * 72];
    __shared__ unsigned s_W9h[32 * 24];
    __shared__ unsigned s_W9l[32 * 24];
    __shared__ __align__(16) float s_stage[8 * 576];
    __shared__ float s_bo[8], s_bw[4], s_bl[64], s_g[64], s_b[64];
    __shared__ float s_obuf[512];

    int tid  = threadIdx.x;
    int w    = tid >> 5, lane = tid & 31;
    int v    = lane >> 2, c = lane & 3;
    int y    = blockIdx.x >> 4;
    int xg   = blockIdx.x & 15;
    int x    = xg * 8 + w;
    int qb   = lane & ~3;

    float T[12];
    #pragma unroll
    for (int r = 0; r < 3; r++)
        #pragma unroll
        for (int q = 0; q < 4; q++)
            T[r*4+q] = intr[r*3+0]*velo[0*4+q] + intr[r*3+1]*velo[1*4+q]
                     + intr[r*3+2]*velo[2*4+q];

    float hx = 0.8f * (float)x;
    float hy = 51.2f - 0.8f * (float)y;
    float hz = 0.5f * (float)v - 2.5f;
    float p0 = T[0]*hx + T[1]*hy + T[2]*hz  + T[3];
    float p1 = T[4]*hx + T[5]*hy + T[6]*hz  + T[7];
    float p2 = T[8]*hx + T[9]*hy + T[10]*hz + T[11];
    float coordx = (p0 / p2) * (1.0f/640.0f) - 1.0f;
    float coordy = (p1 / p2) * (1.0f/192.0f) - 1.0f;

    int vox = x * 1024 + y * 8 + v;
    float bv[16];
    #pragma unroll
    for (int p = 0; p < 8; p++) {
        int e0 = 16*(p>>1) + 8*(p&1) + 2*c;
        float2 q = *(const float2*)(bev_emb + (size_t)vox * 64 + e0);
        bv[2*p] = q.x; bv[2*p+1] = q.y;
    }

    for (int it = 0; it < 3; ++it) {
        __syncthreads();
        // ---- bulk-copy precomputed bf16 tiles ----
        {
            const uint4* gh = (const uint4*)(g_Bh + it*2304);
            const uint4* gl = (const uint4*)(g_Bl + it*2304);
            for (int i = tid; i < 576; i += 256) {
                ((uint4*)s_Bh)[i] = gh[i];
                ((uint4*)s_Bl)[i] = gl[i];
            }
            const uint4* g9h = (const uint4*)(g_W9h + it*768);
            const uint4* g9l = (const uint4*)(g_W9l + it*768);
            for (int i = tid; i < 192; i += 256) {
                ((uint4*)s_W9h)[i] = g9h[i];
                ((uint4*)s_W9l)[i] = g9l[i];
            }
        }
        float sc = soff[it];
        if (tid < 6)                    s_bo[tid]    = boff[it*6 + tid] * sc;
        if (tid >= 32  && tid < 35)     s_bw[tid-32] = bw[it*3 + tid-32];
        if (tid >= 64  && tid < 128)    s_bl[tid-64] = bl[it*64 + tid-64];
        if (tid >= 128 && tid < 192)    s_g[tid-128] = lng[it*64 + tid-128];
        if (tid >= 192)                 s_b[tid-192] = lnb[it*64 + tid-192];
        __syncthreads();

        // ---- pack pre-gather bv into bf16 hi/lo A fragments ----
        unsigned ah0[4], ah2[4], al0[4], al2[4];
        #pragma unroll
        for (int mm = 0; mm < 4; mm++) {
            float x0 = bv[4*mm], x1 = bv[4*mm+1], x2 = bv[4*mm+2], x3 = bv[4*mm+3];
            float h0 = bfr(x0), h1 = bfr(x1), h2 = bfr(x2), h3 = bfr(x3);
            ah0[mm] = pkbf(h0, h1);       ah2[mm] = pkbf(h2, h3);
            al0[mm] = pkbf(x0-h0, x1-h1); al2[mm] = pkbf(x2-h2, x3-h3);
        }

        // ---- 9-output GEMV via mma ----
        float dd0 = 0.f, dd1 = 0.f, dd8 = 0.f, dd9 = 0.f;
        float z2 = 0.f, z3 = 0.f;
        #pragma unroll
        for (int mm = 0; mm < 4; mm++) {
            unsigned bh0 = s_W9h[(8*mm + c)*24 + v];
            unsigned bh1 = s_W9h[(8*mm + 4 + c)*24 + v];
            unsigned bl0_ = s_W9l[(8*mm + c)*24 + v];
            unsigned bl1_ = s_W9l[(8*mm + 4 + c)*24 + v];
            mma16816(dd0, dd1, z2, z3, ah0[mm], ah2[mm], bh0, bh1);
            mma16816(dd0, dd1, z2, z3, al0[mm], al2[mm], bh0, bh1);
            mma16816(dd0, dd1, z2, z3, ah0[mm], ah2[mm], bl0_, bl1_);
        }
        #pragma unroll
        for (int mm = 0; mm < 4; mm++) {
            unsigned bh0 = s_W9h[(8*mm + c)*24 + 8 + v];
            unsigned bh1 = s_W9h[(8*mm + 4 + c)*24 + 8 + v];
            unsigned bl0_ = s_W9l[(8*mm + c)*24 + 8 + v];
            unsigned bl1_ = s_W9l[(8*mm + 4 + c)*24 + 8 + v];
            mma16816(dd8, dd9, z2, z3, ah0[mm], ah2[mm], bh0, bh1);
            mma16816(dd8, dd9, z2, z3, al0[mm], al2[mm], bh0, bh1);
            mma16816(dd8, dd9, z2, z3, ah0[mm], ah2[mm], bl0_, bl1_);
        }
        float d[9];
        #pragma unroll
        for (int t = 0; t < 4; t++) {
            d[2*t]   = __shfl_sync(0xffffffffu, dd0, qb | t);
            d[2*t+1] = __shfl_sync(0xffffffffu, dd1, qb | t);
        }
        d[8] = __shfl_sync(0xffffffffu, dd8, qb);

        // ---- softmax K=3 ----
        float l0 = d[6] + s_bw[0], l1 = d[7] + s_bw[1], l2 = d[8] + s_bw[2];
        float m  = fmaxf(l0, fmaxf(l1, l2));
        float e0 = __expf(l0 - m), e1 = __expf(l1 - m), e2 = __expf(l2 - m);
        float inv = 1.0f / (e0 + e1 + e2);

        float fxk[3], fyk[3], wkk[3];
        wkk[0] = e0 * inv; wkk[1] = e1 * inv; wkk[2] = e2 * inv;
        #pragma unroll
        for (int k = 0; k < 3; k++) {
            float gx = coordx + d[2*k]   * sc + s_bo[2*k];
            float gy = coordy + d[2*k+1] * sc + s_bo[2*k+1];
            fxk[k] = fmaf(gx, 160.f, 159.5f);
            fyk[k] = fmaf(gy, 48.f,  47.5f);
        }

        // ---- line-dense fp16 gather (2 rounds of 4 voxels, 1 line/pixel) ----
        int cc = lane & 7;
        ull A[2][4];
        #pragma unroll
        for (int r = 0; r < 2; r++) {
            A[r][0] = A[r][1] = A[r][2] = A[r][3] = 0ull;
            int src = (((lane >> 3) + 4*r) << 2);
            #pragma unroll
            for (int k = 0; k < 3; k++) {
                float fx = __shfl_sync(0xffffffffu, fxk[k], src);
                float fy = __shfl_sync(0xffffffffu, fyk[k], src);
                float wg = __shfl_sync(0xffffffffu, wkk[k], src);
                float x0f = floorf(fx), y0f = floorf(fy);
                int ix = (int)x0f, iy = (int)y0f;
                float wx1 = fx - x0f, wy1 = fy - y0f;
                float wx0 = 1.f - wx1, wy0 = 1.f - wy1;
                gather8h(ix,   iy,   wx0*wy0*wg, A[r], cc);
                gather8h(ix+1, iy,   wx1*wy0*wg, A[r], cc);
                gather8h(ix,   iy+1, wx0*wy1*wg, A[r], cc);
                gather8h(ix+1, iy+1, wx1*wy1*wg, A[r], cc);
            }
        }
        // stage (channels [8cc,8cc+8) contiguous, stride 72) -> permuted readback
        float* stw = s_stage + w * 576;
        #pragma unroll
        for (int r = 0; r < 2; r++) {
            int vv = (lane >> 3) + 4*r;
            float2 a0 = upk2(A[r][0]), a1 = upk2(A[r][1]);
            float2 a2 = upk2(A[r][2]), a3 = upk2(A[r][3]);
            *(float4*)&stw[vv*72 + cc*8]     = make_float4(a0.x, a0.y, a1.x, a1.y);
            *(float4*)&stw[vv*72 + cc*8 + 4] = make_float4(a2.x, a2.y, a3.x, a3.y);
        }
        __syncwarp();
        #pragma unroll
        for (int p = 0; p < 8; p++) {
            int ep = 16*(p>>1) + 8*(p&1) + 2*c;
            float2 gf = *(const float2*)&stw[v*72 + ep];
            bv[2*p] += gf.x; bv[2*p+1] += gf.y;
        }

        // ==== main matmul via mma: rows=voxels, A/D in resident registers ====
        #pragma unroll
        for (int mm = 0; mm < 4; mm++) {
            float x0 = bv[4*mm], x1 = bv[4*mm+1], x2 = bv[4*mm+2], x3 = bv[4*mm+3];
            float h0 = bfr(x0), h1 = bfr(x1), h2 = bfr(x2), h3 = bfr(x3);
            ah0[mm] = pkbf(h0, h1);       ah2[mm] = pkbf(h2, h3);
            al0[mm] = pkbf(x0-h0, x1-h1); al2[mm] = pkbf(x2-h2, x3-h3);
        }
        float hacc[16];
        #pragma unroll
        for (int n = 0; n < 8; n++) {
            float d0 = 0.f, d1 = 0.f, j2 = 0.f, j3 = 0.f;
            #pragma unroll
            for (int mm = 0; mm < 4; mm++) {
                unsigned bh0 = s_Bh[(8*mm + c)*72 + 8*n + v];
                unsigned bh1 = s_Bh[(8*mm + 4 + c)*72 + 8*n + v];
                unsigned bl0_ = s_Bl[(8*mm + c)*72 + 8*n + v];
                unsigned bl1_ = s_Bl[(8*mm + 4 + c)*72 + 8*n + v];
                mma16816(d0, d1, j2, j3, ah0[mm], ah2[mm], bh0, bh1);
                mma16816(d0, d1, j2, j3, al0[mm], al2[mm], bh0, bh1);
                mma16816(d0, d1, j2, j3, ah0[mm], ah2[mm], bl0_, bl1_);
            }
            hacc[2*n] = d0; hacc[2*n+1] = d1;
        }

        // ---- bias + LayerNorm + residual ----
        float h[16];
        #pragma unroll
        for (int p = 0; p < 8; p++) {
            int ep = 16*(p>>1) + 8*(p&1) + 2*c;
            float2 b2 = *(const float2*)&s_bl[ep];
            h[2*p] = hacc[2*p] + b2.x; h[2*p+1] = hacc[2*p+1] + b2.y;
        }
        float s1 = 0.f, s2 = 0.f;
        #pragma unroll
        for (int i = 0; i < 16; i++) { s1 += h[i]; s2 += h[i]*h[i]; }
        #pragma unroll
        for (int s = 1; s <= 2; s <<= 1) {
            s1 += __shfl_xor_sync(0xffffffffu, s1, s);
            s2 += __shfl_xor_sync(0xffffffffu, s2, s);
        }
        float mu  = s1 * (1.f/64.f);
        float var = s2 * (1.f/64.f) - mu * mu;
        float rs  = rsqrtf(var + 1e-5f);
        #pragma unroll
        for (int p = 0; p < 8; p++) {
            int ep = 16*(p>>1) + 8*(p&1) + 2*c;
            float2 g2 = *(const float2*)&s_g[ep];
            float2 b2 = *(const float2*)&s_b[ep];
            bv[2*p]   += (h[2*p]   - mu) * rs * g2.x + b2.x;
            bv[2*p+1] += (h[2*p+1] - mu) * rs * g2.y + b2.y;
        }
    }

    // ---- mean over z + store ----
    #pragma unroll
    for (int i = 0; i < 16; i++) {
        float s = bv[i];
        s += __shfl_xor_sync(0xffffffffu, s, 4);
        s += __shfl_xor_sync(0xffffffffu, s, 8);
        s += __shfl_xor_sync(0xffffffffu, s, 16);
        bv[i] = s;
    }
    if (v == 0) {
        #pragma unroll
        for (int i = 0; i < 16; i++) {
            int e = 16*(i>>2) + 8*((i>>1)&1) + 2*c + (i&1);
            s_obuf[e * 8 + w] = bv[i] * 0.125f;
        }
    }
    __syncthreads();
    for (int idx = tid; idx < 512; idx += 256) {
        int e = idx >> 3, xi = idx & 7;
        out[(size_t)e * 16384 + y * 128 + xg * 8 + xi] = s_obuf[idx];
    }
}

extern "C" void kernel_launch(void* const* d_in, const int* in_sizes, int n_in,
                              void* d_out, int out_size) {
    const float* velo = (const float*)d_in[0];
    const float* intr = (const float*)d_in[1];
    const float* img  = (const float*)d_in[2];
    const float* bev  = (const float*)d_in[3];
    const float* Woff = (const float*)d_in[4];
    const float* boff = (const float*)d_in[5];
    const float* soff = (const float*)d_in[6];
    const float* Ww   = (const float*)d_in[7];
    const float* bw   = (const float*)d_in[8];
    const float* Wl   = (const float*)d_in[9];
    const float* bl   = (const float*)d_in[10];
    const float* lng  = (const float*)d_in[11];
    const float* lnb  = (const float*)d_in[12];

    prologue_kernel<<<963, 256>>>(img, Wl, Woff, Ww);
    bev_kernel<<<2048, 256>>>(velo, intr, bev, boff, soff,
                              bw, bl, lng, lnb, (float*)d_out);
}

// round 12
// speedup vs baseline: 1.2664x; 1.2664x over previous
#include <cuda_runtime.h>
#include <cuda_bf16.h>

#define FHh 96
#define FWw 320
#define NPIX (FHh*FWw)

__device__ float g_imgT[NPIX * 64];           // [pixel][64ch] fp32, 256B rows
__device__ unsigned g_Bh[3 * 2304];           // Wl pairs, rows e/2 x stride 72
__device__ unsigned g_Bl[3 * 2304];
__device__ unsigned g_W9h[3 * 768];           // W9 pairs, rows e/2 x stride 24
__device__ unsigned g_W9l[3 * 768];

typedef unsigned long long ull;

static __device__ __forceinline__ ull pk2(float x, float y) {
    ull r; asm("mov.b64 %0,{%1,%2};" : "=l"(r) : "f"(x), "f"(y)); return r;
}
static __device__ __forceinline__ float2 upk2(ull v) {
    float2 r; asm("mov.b64 {%0,%1},%2;" : "=f"(r.x), "=f"(r.y) : "l"(v)); return r;
}
static __device__ __forceinline__ void fma2(ull &d, ull a, ull b) {
    asm("fma.rn.f32x2 %0,%1,%2,%0;" : "+l"(d) : "l"(a), "l"(b));
}
static __device__ __forceinline__ unsigned pkbf(float lo, float hi) {
    unsigned r; asm("cvt.rn.bf16x2.f32 %0, %1, %2;" : "=r"(r) : "f"(hi), "f"(lo)); return r;
}
static __device__ __forceinline__ void mma_full(float &d0, float &d1, float &d2, float &d3,
                                                unsigned a0, unsigned a1,
                                                unsigned a2, unsigned a3,
                                                unsigned b0, unsigned b1) {
    asm volatile("mma.sync.aligned.m16n8k16.row.col.f32.bf16.bf16.f32 "
                 "{%0,%1,%2,%3},{%4,%5,%6,%7},{%8,%9},{%0,%1,%2,%3};"
                 : "+f"(d0), "+f"(d1), "+f"(d2), "+f"(d3)
                 : "r"(a0), "r"(a1), "r"(a2), "r"(a3), "r"(b0), "r"(b1));
}
static __device__ __forceinline__ float bfr(float x) {
    return __bfloat162float(__float2bfloat16(x));
}

// ---------- prologue: fp32 transpose (blocks 0-959) + weight prep (960-962) ----
__global__ void prologue_kernel(const float* __restrict__ src,
                                const float* __restrict__ Wl,
                                const float* __restrict__ Woff,
                                const float* __restrict__ Ww) {
    int b = blockIdx.x, tid = threadIdx.x;
    if (b < 960) {
        __shared__ float t[64][33];
        int p0 = b * 32;
        int tx = tid & 31, ty = tid >> 5;
        #pragma unroll
        for (int r = 0; r < 64; r += 8)
            t[ty + r][tx] = src[(size_t)(ty + r) * NPIX + p0 + tx];
        __syncthreads();
        #pragma unroll
        for (int i = 0; i < 4; i++) {
            int idx = tid + i * 256;           // 0..1023
            int px = idx >> 5, e2 = idx & 31;
            *(float2*)&g_imgT[(size_t)(p0 + px) * 64 + 2*e2] =
                make_float2(t[2*e2][px], t[2*e2+1][px]);
        }
    } else {
        int it = b - 960;
        for (int idx = tid; idx < 2048; idx += 256) {
            int e2 = idx >> 6, j = idx & 63;
            float a = Wl[it*4096 + (2*e2)*64 + j];
            float bb = Wl[it*4096 + (2*e2+1)*64 + j];
            float ha = bfr(a), hb = bfr(bb);
            g_Bh[it*2304 + e2*72 + j] = pkbf(ha, hb);
            g_Bl[it*2304 + e2*72 + j] = pkbf(a - ha, bb - hb);
        }
        for (int idx = tid; idx < 512; idx += 256) {
            int e2 = idx >> 4, j = idx & 15;
            float a = 0.f, bb = 0.f;
            if (j < 6)      { a = Woff[it*384 + (2*e2)*6 + j];   bb = Woff[it*384 + (2*e2+1)*6 + j]; }
            else if (j < 9) { a = Ww[it*192 + (2*e2)*3 + (j-6)]; bb = Ww[it*192 + (2*e2+1)*3 + (j-6)]; }
            float ha = bfr(a), hb = bfr(bb);
            g_W9h[it*768 + e2*24 + j] = pkbf(ha, hb);
            g_W9l[it*768 + e2*24 + j] = pkbf(a - ha, bb - hb);
        }
    }
}

// fp32 corner gather: lane cc covers channels [4cc,4cc+4) and [32+4cc,+4)
static __device__ __forceinline__ void gather8(int cx, int cy, float wgt,
                                               ull A[4], int cc) {
    if ((unsigned)cx < (unsigned)FWw && (unsigned)cy < (unsigned)FHh) {
        const float* p = &g_imgT[(size_t)(cy * FWw + cx) * 64];
        ulonglong2 qlo = *(const ulonglong2*)(p + cc * 4);
        ulonglong2 qhi = *(const ulonglong2*)(p + 32 + cc * 4);
        ull w2 = pk2(wgt, wgt);
        fma2(A[0], w2, qlo.x); fma2(A[1], w2, qlo.y);
        fma2(A[2], w2, qhi.x); fma2(A[3], w2, qhi.y);
    }
}

// Warp = TWO z-columns (x_a = base, x_b = base+1), 16 voxels.
// lane = v*4+c. MMA rows 0-7 = col A voxels, rows 8-15 = col B voxels.
// PERMUTED channels: bv[4m+{0..3}] (col A) = ch {16m+2c,+1, 16m+8+2c,+1};
// bv[16+...] same for col B.
__global__ __launch_bounds__(256, 2) void bev_kernel(
    const float* __restrict__ velo,  const float* __restrict__ intr,
    const float* __restrict__ bev_emb,
    const float* __restrict__ boff,  const float* __restrict__ soff,
    const float* __restrict__ bw,    const float* __restrict__ bl,
    const float* __restrict__ lng,   const float* __restrict__ lnb,
    float* __restrict__ out)
{
    __shared__ unsigned s_Bh[32 * 72];
    __shared__ unsigned s_Bl[32 * 72];
    __shared__ unsigned s_W9h[32 * 24];
    __shared__ unsigned s_W9l[32 * 24];
    __shared__ __align__(16) float s_stage[8 * 576];   // also reused as obuf
    __shared__ float s_bo[8], s_bw[4], s_bl[64], s_g[64], s_b[64];

    int tid  = threadIdx.x;
    int w    = tid >> 5, lane = tid & 31;
    int v    = lane >> 2, c = lane & 3;
    int y    = blockIdx.x >> 3;
    int xg   = blockIdx.x & 7;
    int xa   = xg * 16 + w * 2;       // col A
    int qb   = lane & ~3;

    float T[12];
    #pragma unroll
    for (int r = 0; r < 3; r++)
        #pragma unroll
        for (int q = 0; q < 4; q++)
            T[r*4+q] = intr[r*3+0]*velo[0*4+q] + intr[r*3+1]*velo[1*4+q]
                     + intr[r*3+2]*velo[2*4+q];

    float hz = 0.5f * (float)v - 2.5f;
    float hy = 51.2f - 0.8f * (float)y;
    float cxA, cyA, cxB, cyB;
    {
        float hxA = 0.8f * (float)xa;
        float p0 = T[0]*hxA + T[1]*hy + T[2]*hz  + T[3];
        float p1 = T[4]*hxA + T[5]*hy + T[6]*hz  + T[7];
        float p2 = T[8]*hxA + T[9]*hy + T[10]*hz + T[11];
        cxA = (p0 / p2) * (1.0f/640.0f) - 1.0f;
        cyA = (p1 / p2) * (1.0f/192.0f) - 1.0f;
        float hxB = hxA + 0.8f;
        p0 = T[0]*hxB + T[1]*hy + T[2]*hz  + T[3];
        p1 = T[4]*hxB + T[5]*hy + T[6]*hz  + T[7];
        p2 = T[8]*hxB + T[9]*hy + T[10]*hz + T[11];
        cxB = (p0 / p2) * (1.0f/640.0f) - 1.0f;
        cyB = (p1 / p2) * (1.0f/192.0f) - 1.0f;
    }

    float bv[32];
    #pragma unroll
    for (int col = 0; col < 2; col++) {
        int vox = (xa + col) * 1024 + y * 8 + v;
        #pragma unroll
        for (int p = 0; p < 8; p++) {
            int e0 = 16*(p>>1) + 8*(p&1) + 2*c;
            float2 q = *(const float2*)(bev_emb + (size_t)vox * 64 + e0);
            bv[16*col + 2*p] = q.x; bv[16*col + 2*p+1] = q.y;
        }
    }

    for (int it = 0; it < 3; ++it) {
        __syncthreads();
        {
            const uint4* gh = (const uint4*)(g_Bh + it*2304);
            const uint4* gl = (const uint4*)(g_Bl + it*2304);
            for (int i = tid; i < 576; i += 256) {
                ((uint4*)s_Bh)[i] = gh[i];
                ((uint4*)s_Bl)[i] = gl[i];
            }
            const uint4* g9h = (const uint4*)(g_W9h + it*768);
            const uint4* g9l = (const uint4*)(g_W9l + it*768);
            for (int i = tid; i < 192; i += 256) {
                ((uint4*)s_W9h)[i] = g9h[i];
                ((uint4*)s_W9l)[i] = g9l[i];
            }
        }
        float sc = soff[it];
        if (tid < 6)                    s_bo[tid]    = boff[it*6 + tid] * sc;
        if (tid >= 32  && tid < 35)     s_bw[tid-32] = bw[it*3 + tid-32];
        if (tid >= 64  && tid < 128)    s_bl[tid-64] = bl[it*64 + tid-64];
        if (tid >= 128 && tid < 192)    s_g[tid-128] = lng[it*64 + tid-128];
        if (tid >= 192)                 s_b[tid-192] = lnb[it*64 + tid-192];
        __syncthreads();

        // ---- pack bv (both columns) into bf16 hi/lo A fragments ----
        unsigned ah[4][4], al[4][4];
        #pragma unroll
        for (int mm = 0; mm < 4; mm++) {
            float xa0 = bv[4*mm],    xa1 = bv[4*mm+1],  xa2 = bv[4*mm+2],  xa3 = bv[4*mm+3];
            float xb0 = bv[16+4*mm], xb1 = bv[17+4*mm], xb2 = bv[18+4*mm], xb3 = bv[19+4*mm];
            float ha0 = bfr(xa0), ha1 = bfr(xa1), ha2 = bfr(xa2), ha3 = bfr(xa3);
            float hb0 = bfr(xb0), hb1 = bfr(xb1), hb2 = bfr(xb2), hb3 = bfr(xb3);
            ah[mm][0] = pkbf(ha0, ha1); ah[mm][1] = pkbf(hb0, hb1);
            ah[mm][2] = pkbf(ha2, ha3); ah[mm][3] = pkbf(hb2, hb3);
            al[mm][0] = pkbf(xa0-ha0, xa1-ha1); al[mm][1] = pkbf(xb0-hb0, xb1-hb1);
            al[mm][2] = pkbf(xa2-ha2, xa3-ha3); al[mm][3] = pkbf(xb2-hb2, xb3-hb3);
        }

        // ---- 9-output GEMV via mma (both columns at once) ----
        float g0 = 0.f, g1 = 0.f, g2 = 0.f, g3 = 0.f;
        float q0 = 0.f, q1 = 0.f, q2 = 0.f, q3 = 0.f;
        #pragma unroll
        for (int mm = 0; mm < 4; mm++) {
            unsigned bh0 = s_W9h[(8*mm + c)*24 + v];
            unsigned bh1 = s_W9h[(8*mm + 4 + c)*24 + v];
            unsigned bl0_ = s_W9l[(8*mm + c)*24 + v];
            unsigned bl1_ = s_W9l[(8*mm + 4 + c)*24 + v];
            mma_full(g0,g1,g2,g3, ah[mm][0],ah[mm][1],ah[mm][2],ah[mm][3], bh0,bh1);
            mma_full(g0,g1,g2,g3, al[mm][0],al[mm][1],al[mm][2],al[mm][3], bh0,bh1);
            mma_full(g0,g1,g2,g3, ah[mm][0],ah[mm][1],ah[mm][2],ah[mm][3], bl0_,bl1_);
        }
        #pragma unroll
        for (int mm = 0; mm < 4; mm++) {
            unsigned bh0 = s_W9h[(8*mm + c)*24 + 8 + v];
            unsigned bh1 = s_W9h[(8*mm + 4 + c)*24 + 8 + v];
            unsigned bl0_ = s_W9l[(8*mm + c)*24 + 8 + v];
            unsigned bl1_ = s_W9l[(8*mm + 4 + c)*24 + 8 + v];
            mma_full(q0,q1,q2,q3, ah[mm][0],ah[mm][1],ah[mm][2],ah[mm][3], bh0,bh1);
            mma_full(q0,q1,q2,q3, al[mm][0],al[mm][1],al[mm][2],al[mm][3], bh0,bh1);
            mma_full(q0,q1,q2,q3, ah[mm][0],ah[mm][1],ah[mm][2],ah[mm][3], bl0_,bl1_);
        }
        float dA[9], dB[9];
        #pragma unroll
        for (int t = 0; t < 4; t++) {
            dA[2*t]   = __shfl_sync(0xffffffffu, g0, qb | t);
            dA[2*t+1] = __shfl_sync(0xffffffffu, g1, qb | t);
            dB[2*t]   = __shfl_sync(0xffffffffu, g2, qb | t);
            dB[2*t+1] = __shfl_sync(0xffffffffu, g3, qb | t);
        }
        dA[8] = __shfl_sync(0xffffffffu, q0, qb);
        dB[8] = __shfl_sync(0xffffffffu, q2, qb);

        // ---- softmax + coords for both columns ----
        float fxkA[3], fykA[3], wkkA[3], fxkB[3], fykB[3], wkkB[3];
        {
            float l0 = dA[6] + s_bw[0], l1 = dA[7] + s_bw[1], l2 = dA[8] + s_bw[2];
            float m  = fmaxf(l0, fmaxf(l1, l2));
            float e0 = __expf(l0 - m), e1 = __expf(l1 - m), e2 = __expf(l2 - m);
            float inv = 1.0f / (e0 + e1 + e2);
            wkkA[0] = e0*inv; wkkA[1] = e1*inv; wkkA[2] = e2*inv;
            #pragma unroll
            for (int k = 0; k < 3; k++) {
                float gx = cxA + dA[2*k]   * sc + s_bo[2*k];
                float gy = cyA + dA[2*k+1] * sc + s_bo[2*k+1];
                fxkA[k] = fmaf(gx, 160.f, 159.5f);
                fykA[k] = fmaf(gy, 48.f,  47.5f);
            }
            l0 = dB[6] + s_bw[0]; l1 = dB[7] + s_bw[1]; l2 = dB[8] + s_bw[2];
            m  = fmaxf(l0, fmaxf(l1, l2));
            e0 = __expf(l0 - m); e1 = __expf(l1 - m); e2 = __expf(l2 - m);
            inv = 1.0f / (e0 + e1 + e2);
            wkkB[0] = e0*inv; wkkB[1] = e1*inv; wkkB[2] = e2*inv;
            #pragma unroll
            for (int k = 0; k < 3; k++) {
                float gx = cxB + dB[2*k]   * sc + s_bo[2*k];
                float gy = cyB + dB[2*k+1] * sc + s_bo[2*k+1];
                fxkB[k] = fmaf(gx, 160.f, 159.5f);
                fykB[k] = fmaf(gy, 48.f,  47.5f);
            }
        }

        // ---- gather: 2 phases (col A, col B), each 2 rounds of 4 voxels ----
        int cc = lane & 7;
        float* stw = s_stage + w * 576;
        #pragma unroll
        for (int half = 0; half < 2; half++) {
            ull A[2][4];
            #pragma unroll
            for (int r = 0; r < 2; r++) {
                A[r][0] = A[r][1] = A[r][2] = A[r][3] = 0ull;
                int src = (((lane >> 3) + 4*r) << 2);
                #pragma unroll
                for (int k = 0; k < 3; k++) {
                    float fx = __shfl_sync(0xffffffffu, half ? fxkB[k] : fxkA[k], src);
                    float fy = __shfl_sync(0xffffffffu, half ? fykB[k] : fykA[k], src);
                    float wg = __shfl_sync(0xffffffffu, half ? wkkB[k] : wkkA[k], src);
                    float x0f = floorf(fx), y0f = floorf(fy);
                    int ix = (int)x0f, iy = (int)y0f;
                    float wx1 = fx - x0f, wy1 = fy - y0f;
                    float wx0 = 1.f - wx1, wy0 = 1.f - wy1;
                    gather8(ix,   iy,   wx0*wy0*wg, A[r], cc);
                    gather8(ix+1, iy,   wx1*wy0*wg, A[r], cc);
                    gather8(ix,   iy+1, wx0*wy1*wg, A[r], cc);
                    gather8(ix+1, iy+1, wx1*wy1*wg, A[r], cc);
                }
            }
            #pragma unroll
            for (int r = 0; r < 2; r++) {
                int vv = (lane >> 3) + 4*r;
                float2 lo0 = upk2(A[r][0]), lo1 = upk2(A[r][1]);
                float2 hi0 = upk2(A[r][2]), hi1 = upk2(A[r][3]);
                *(float4*)&stw[vv*72 + cc*4]      = make_float4(lo0.x, lo0.y, lo1.x, lo1.y);
                *(float4*)&stw[vv*72 + 32 + cc*4] = make_float4(hi0.x, hi0.y, hi1.x, hi1.y);
            }
            __syncwarp();
            #pragma unroll
            for (int p = 0; p < 8; p++) {
                int ep = 16*(p>>1) + 8*(p&1) + 2*c;
                float2 gf = *(const float2*)&stw[v*72 + ep];
                bv[16*half + 2*p] += gf.x; bv[16*half + 2*p+1] += gf.y;
            }
            __syncwarp();
        }

        // ---- re-pack A fragments (post-gather bv) ----
        #pragma unroll
        for (int mm = 0; mm < 4; mm++) {
            float xa0 = bv[4*mm],    xa1 = bv[4*mm+1],  xa2 = bv[4*mm+2],  xa3 = bv[4*mm+3];
            float xb0 = bv[16+4*mm], xb1 = bv[17+4*mm], xb2 = bv[18+4*mm], xb3 = bv[19+4*mm];
            float ha0 = bfr(xa0), ha1 = bfr(xa1), ha2 = bfr(xa2), ha3 = bfr(xa3);
            float hb0 = bfr(xb0), hb1 = bfr(xb1), hb2 = bfr(xb2), hb3 = bfr(xb3);
            ah[mm][0] = pkbf(ha0, ha1); ah[mm][1] = pkbf(hb0, hb1);
            ah[mm][2] = pkbf(ha2, ha3); ah[mm][3] = pkbf(hb2, hb3);
            al[mm][0] = pkbf(xa0-ha0, xa1-ha1); al[mm][1] = pkbf(xb0-hb0, xb1-hb1);
            al[mm][2] = pkbf(xa2-ha2, xa3-ha3); al[mm][3] = pkbf(xb2-hb2, xb3-hb3);
        }

        // ==== main matmul: 24 MMAs serve 16 voxels ====
        float hA[16], hB[16];
        #pragma unroll
        for (int n = 0; n < 8; n++) {
            float d0 = 0.f, d1 = 0.f, d2 = 0.f, d3 = 0.f;
            #pragma unroll
            for (int mm = 0; mm < 4; mm++) {
                unsigned bh0 = s_Bh[(8*mm + c)*72 + 8*n + v];
                unsigned bh1 = s_Bh[(8*mm + 4 + c)*72 + 8*n + v];
                unsigned bl0_ = s_Bl[(8*mm + c)*72 + 8*n + v];
                unsigned bl1_ = s_Bl[(8*mm + 4 + c)*72 + 8*n + v];
                mma_full(d0,d1,d2,d3, ah[mm][0],ah[mm][1],ah[mm][2],ah[mm][3], bh0,bh1);
                mma_full(d0,d1,d2,d3, al[mm][0],al[mm][1],al[mm][2],al[mm][3], bh0,bh1);
                mma_full(d0,d1,d2,d3, ah[mm][0],ah[mm][1],ah[mm][2],ah[mm][3], bl0_,bl1_);
            }
            hA[2*n] = d0; hA[2*n+1] = d1;
            hB[2*n] = d2; hB[2*n+1] = d3;
        }

        // ---- bias + LayerNorm + residual, both columns ----
        #pragma unroll
        for (int col = 0; col < 2; col++) {
            float* hh = col ? hB : hA;
            float s1 = 0.f, s2 = 0.f;
            #pragma unroll
            for (int p = 0; p < 8; p++) {
                int ep = 16*(p>>1) + 8*(p&1) + 2*c;
                float2 b2 = *(const float2*)&s_bl[ep];
                hh[2*p] += b2.x; hh[2*p+1] += b2.y;
            }
            #pragma unroll
            for (int i = 0; i < 16; i++) { s1 += hh[i]; s2 += hh[i]*hh[i]; }
            #pragma unroll
            for (int s = 1; s <= 2; s <<= 1) {
                s1 += __shfl_xor_sync(0xffffffffu, s1, s);
                s2 += __shfl_xor_sync(0xffffffffu, s2, s);
            }
            float mu  = s1 * (1.f/64.f);
            float var = s2 * (1.f/64.f) - mu * mu;
            float rs  = rsqrtf(var + 1e-5f);
            #pragma unroll
            for (int p = 0; p < 8; p++) {
                int ep = 16*(p>>1) + 8*(p&1) + 2*c;
                float2 g2 = *(const float2*)&s_g[ep];
                float2 b2 = *(const float2*)&s_b[ep];
                bv[16*col + 2*p]   += (hh[2*p]   - mu) * rs * g2.x + b2.x;
                bv[16*col + 2*p+1] += (hh[2*p+1] - mu) * rs * g2.y + b2.y;
            }
        }
    }

    // ---- mean over z (both columns) + store ----
    #pragma unroll
    for (int i = 0; i < 32; i++) {
        float s = bv[i];
        s += __shfl_xor_sync(0xffffffffu, s, 4);
        s += __shfl_xor_sync(0xffffffffu, s, 8);
        s += __shfl_xor_sync(0xffffffffu, s, 16);
        bv[i] = s;
    }
    __syncthreads();                 // all stage reads done before obuf overlay
    float* obuf = s_stage;           // reuse staging region (first 1024 floats)
    if (v == 0) {
        #pragma unroll
        for (int i = 0; i < 16; i++) {
            int e = 16*(i>>2) + 8*((i>>1)&1) + 2*c + (i&1);
            obuf[e * 16 + 2*w]     = bv[i]      * 0.125f;
            obuf[e * 16 + 2*w + 1] = bv[16 + i] * 0.125f;
        }
    }
    __syncthreads();
    for (int idx = tid; idx < 1024; idx += 256) {
        int e = idx >> 4, xi = idx & 15;
        out[(size_t)e * 16384 + y * 128 + xg * 16 + xi] = obuf[idx];
    }
}

extern "C" void kernel_launch(void* const* d_in, const int* in_sizes, int n_in,
                              void* d_out, int out_size) {
    const float* velo = (const float*)d_in[0];
    const float* intr = (const float*)d_in[1];
    const float* img  = (const float*)d_in[2];
    const float* bev  = (const float*)d_in[3];
    const float* Woff = (const float*)d_in[4];
    const float* boff = (const float*)d_in[5];
    const float* soff = (const float*)d_in[6];
    const float* Ww   = (const float*)d_in[7];
    const float* bw   = (const float*)d_in[8];
    const float* Wl   = (const float*)d_in[9];
    const float* bl   = (const float*)d_in[10];
    const float* lng  = (const float*)d_in[11];
    const float* lnb  = (const float*)d_in[12];

    prologue_kernel<<<963, 256>>>(img, Wl, Woff, Ww);
    bev_kernel<<<1024, 256>>>(velo, intr, bev, boff, soff,
                              bw, bl, lng, lnb, (float*)d_out);
}

// round 13
// speedup vs baseline: 1.2714x; 1.0040x over previous
#include <cuda_runtime.h>
#include <cuda_bf16.h>

#define FHh 96
#define FWw 320
#define NPIX (FHh*FWw)

__device__ float g_imgT[NPIX * 64];           // [pixel][64ch] fp32, 256B rows
// paired B tiles: uint2 = (k-rows 16mm+2c..+1, 16mm+8+2c..+1) bf16x2 pair
__device__ uint2 g_Bph[3][16 * 68];           // [(mm*4+c)*68 + n*8 + v]
__device__ uint2 g_Bpl[3][16 * 68];
__device__ uint2 g_W9ph[3][16 * 20];          // [(mm*4+c)*20 + n*8 + v], n<2
__device__ uint2 g_W9pl[3][16 * 20];

typedef unsigned long long ull;

static __device__ __forceinline__ ull pk2(float x, float y) {
    ull r; asm("mov.b64 %0,{%1,%2};" : "=l"(r) : "f"(x), "f"(y)); return r;
}
static __device__ __forceinline__ float2 upk2(ull v) {
    float2 r; asm("mov.b64 {%0,%1},%2;" : "=f"(r.x), "=f"(r.y) : "l"(v)); return r;
}
static __device__ __forceinline__ void fma2(ull &d, ull a, ull b) {
    asm("fma.rn.f32x2 %0,%1,%2,%0;" : "+l"(d) : "l"(a), "l"(b));
}
static __device__ __forceinline__ unsigned pkbf(float lo, float hi) {
    unsigned r; asm("cvt.rn.bf16x2.f32 %0, %1, %2;" : "=r"(r) : "f"(hi), "f"(lo)); return r;
}
static __device__ __forceinline__ void mma_full(float &d0, float &d1, float &d2, float &d3,
                                                unsigned a0, unsigned a1,
                                                unsigned a2, unsigned a3,
                                                unsigned b0, unsigned b1) {
    asm volatile("mma.sync.aligned.m16n8k16.row.col.f32.bf16.bf16.f32 "
                 "{%0,%1,%2,%3},{%4,%5,%6,%7},{%8,%9},{%0,%1,%2,%3};"
                 : "+f"(d0), "+f"(d1), "+f"(d2), "+f"(d3)
                 : "r"(a0), "r"(a1), "r"(a2), "r"(a3), "r"(b0), "r"(b1));
}
static __device__ __forceinline__ float bfr(float x) {
    return __bfloat162float(__float2bfloat16(x));
}

// weight element for the 9-col GEMV matrix
static __device__ __forceinline__ float w9el(const float* Woff, const float* Ww,
                                             int it, int e, int j) {
    if (j < 6) return Woff[it*384 + e*6 + j];
    if (j < 9) return Ww[it*192 + e*3 + (j-6)];
    return 0.f;
}

// ---------- prologue: fp32 transpose (blocks 0-959) + paired weight prep ----
__global__ void prologue_kernel(const float* __restrict__ src,
                                const float* __restrict__ Wl,
                                const float* __restrict__ Woff,
                                const float* __restrict__ Ww) {
    int b = blockIdx.x, tid = threadIdx.x;
    if (b < 960) {
        __shared__ float t[64][33];
        int p0 = b * 32;
        int tx = tid & 31, ty = tid >> 5;
        #pragma unroll
        for (int r = 0; r < 64; r += 8)
            t[ty + r][tx] = src[(size_t)(ty + r) * NPIX + p0 + tx];
        __syncthreads();
        #pragma unroll
        for (int i = 0; i < 4; i++) {
            int idx = tid + i * 256;
            int px = idx >> 5, e2 = idx & 31;
            *(float2*)&g_imgT[(size_t)(p0 + px) * 64 + 2*e2] =
                make_float2(t[2*e2][px], t[2*e2+1][px]);
        }
    } else {
        int it = b - 960;
        // main B pairs: (mm,c,n,v) -> 1024 entries
        for (int idx = tid; idx < 1024; idx += 256) {
            int v  = idx & 7, n = (idx >> 3) & 7, c = (idx >> 6) & 3, mm = idx >> 8;
            int col = 8*n + v;
            int eA = 16*mm + 2*c, eB = 16*mm + 8 + 2*c;
            float a0 = Wl[it*4096 + eA*64 + col],     a1 = Wl[it*4096 + (eA+1)*64 + col];
            float b0 = Wl[it*4096 + eB*64 + col],     b1 = Wl[it*4096 + (eB+1)*64 + col];
            float h0 = bfr(a0), h1 = bfr(a1), h2 = bfr(b0), h3 = bfr(b1);
            int o = (mm*4 + c)*68 + n*8 + v;
            g_Bph[it][o] = make_uint2(pkbf(h0, h1), pkbf(h2, h3));
            g_Bpl[it][o] = make_uint2(pkbf(a0-h0, a1-h1), pkbf(b0-h2, b1-h3));
        }
        // GEMV pairs: (mm,c,n<2,v) -> 256 entries
        for (int idx = tid; idx < 256; idx += 256) {
            int v  = idx & 7, n = (idx >> 3) & 1, c = (idx >> 4) & 3, mm = idx >> 6;
            int j = 8*n + v;
            int eA = 16*mm + 2*c, eB = 16*mm + 8 + 2*c;
            float a0 = w9el(Woff, Ww, it, eA,   j), a1 = w9el(Woff, Ww, it, eA+1, j);
            float b0 = w9el(Woff, Ww, it, eB,   j), b1 = w9el(Woff, Ww, it, eB+1, j);
            float h0 = bfr(a0), h1 = bfr(a1), h2 = bfr(b0), h3 = bfr(b1);
            int o = (mm*4 + c)*20 + n*8 + v;
            g_W9ph[it][o] = make_uint2(pkbf(h0, h1), pkbf(h2, h3));
            g_W9pl[it][o] = make_uint2(pkbf(a0-h0, a1-h1), pkbf(b0-h2, b1-h3));
        }
    }
}

// fp32 corner gather: lane cc covers channels [4cc,4cc+4) and [32+4cc,+4)
static __device__ __forceinline__ void gather8(int cx, int cy, float wgt,
                                               ull A[4], int cc) {
    if ((unsigned)cx < (unsigned)FWw && (unsigned)cy < (unsigned)FHh) {
        const float* p = &g_imgT[(size_t)(cy * FWw + cx) * 64];
        ulonglong2 qlo = *(const ulonglong2*)(p + cc * 4);
        ulonglong2 qhi = *(const ulonglong2*)(p + 32 + cc * 4);
        ull w2 = pk2(wgt, wgt);
        fma2(A[0], w2, qlo.x); fma2(A[1], w2, qlo.y);
        fma2(A[2], w2, qhi.x); fma2(A[3], w2, qhi.y);
    }
}

// Warp = TWO z-columns (16 voxels). lane = v*4+c.
// MMA rows 0-7 = col A voxels, rows 8-15 = col B voxels.
// PERMUTED channels: bv[4m+{0..3}] (col A) = ch {16m+2c,+1, 16m+8+2c,+1};
// bv[16+...] same for col B.
__global__ __launch_bounds__(256, 2) void bev_kernel(
    const float* __restrict__ velo,  const float* __restrict__ intr,
    const float* __restrict__ bev_emb,
    const float* __restrict__ boff,  const float* __restrict__ soff,
    const float* __restrict__ bw,    const float* __restrict__ bl,
    const float* __restrict__ lng,   const float* __restrict__ lnb,
    float* __restrict__ out)
{
    __shared__ uint2 s_Bph[16 * 68];
    __shared__ uint2 s_Bpl[16 * 68];
    __shared__ uint2 s_W9ph[16 * 20];
    __shared__ uint2 s_W9pl[16 * 20];
    __shared__ __align__(16) float s_stage[8 * 576];   // also reused as obuf
    __shared__ float s_bo[8], s_bw[4], s_bl[64], s_g[64], s_b[64];

    int tid  = threadIdx.x;
    int w    = tid >> 5, lane = tid & 31;
    int v    = lane >> 2, c = lane & 3;
    int y    = blockIdx.x >> 3;
    int xg   = blockIdx.x & 7;
    int xa   = xg * 16 + w * 2;       // col A
    int qb   = lane & ~3;
    int bofB = c*68 + v;              // base offset for paired B loads
    int bof9 = c*20 + v;

    float T[12];
    #pragma unroll
    for (int r = 0; r < 3; r++)
        #pragma unroll
        for (int q = 0; q < 4; q++)
            T[r*4+q] = intr[r*3+0]*velo[0*4+q] + intr[r*3+1]*velo[1*4+q]
                     + intr[r*3+2]*velo[2*4+q];

    float hz = 0.5f * (float)v - 2.5f;
    float hy = 51.2f - 0.8f * (float)y;
    float cxA, cyA, cxB, cyB;
    {
        float hxA = 0.8f * (float)xa;
        float p0 = T[0]*hxA + T[1]*hy + T[2]*hz  + T[3];
        float p1 = T[4]*hxA + T[5]*hy + T[6]*hz  + T[7];
        float p2 = T[8]*hxA + T[9]*hy + T[10]*hz + T[11];
        cxA = (p0 / p2) * (1.0f/640.0f) - 1.0f;
        cyA = (p1 / p2) * (1.0f/192.0f) - 1.0f;
        float hxB = hxA + 0.8f;
        p0 = T[0]*hxB + T[1]*hy + T[2]*hz  + T[3];
        p1 = T[4]*hxB + T[5]*hy + T[6]*hz  + T[7];
        p2 = T[8]*hxB + T[9]*hy + T[10]*hz + T[11];
        cxB = (p0 / p2) * (1.0f/640.0f) - 1.0f;
        cyB = (p1 / p2) * (1.0f/192.0f) - 1.0f;
    }

    float bv[32];
    #pragma unroll
    for (int col = 0; col < 2; col++) {
        int vox = (xa + col) * 1024 + y * 8 + v;
        #pragma unroll
        for (int p = 0; p < 8; p++) {
            int e0 = 16*(p>>1) + 8*(p&1) + 2*c;
            float2 q = *(const float2*)(bev_emb + (size_t)vox * 64 + e0);
            bv[16*col + 2*p] = q.x; bv[16*col + 2*p+1] = q.y;
        }
    }

    for (int it = 0; it < 3; ++it) {
        __syncthreads();
        {
            const uint4* gh = (const uint4*)g_Bph[it];
            const uint4* gl = (const uint4*)g_Bpl[it];
            for (int i = tid; i < 544; i += 256) {
                ((uint4*)s_Bph)[i] = gh[i];
                ((uint4*)s_Bpl)[i] = gl[i];
            }
            const uint4* g9h = (const uint4*)g_W9ph[it];
            const uint4* g9l = (const uint4*)g_W9pl[it];
            for (int i = tid; i < 160; i += 256) {
                ((uint4*)s_W9ph)[i] = g9h[i];
                ((uint4*)s_W9pl)[i] = g9l[i];
            }
        }
        float sc = soff[it];
        if (tid < 6)                    s_bo[tid]    = boff[it*6 + tid] * sc;
        if (tid >= 32  && tid < 35)     s_bw[tid-32] = bw[it*3 + tid-32];
        if (tid >= 64  && tid < 128)    s_bl[tid-64] = bl[it*64 + tid-64];
        if (tid >= 128 && tid < 192)    s_g[tid-128] = lng[it*64 + tid-128];
        if (tid >= 192)                 s_b[tid-192] = lnb[it*64 + tid-192];
        __syncthreads();

        // ---- pack bv (both columns) into bf16 hi/lo A fragments ----
        unsigned ah[4][4], al[4][4];
        #pragma unroll
        for (int mm = 0; mm < 4; mm++) {
            float xa0 = bv[4*mm],    xa1 = bv[4*mm+1],  xa2 = bv[4*mm+2],  xa3 = bv[4*mm+3];
            float xb0 = bv[16+4*mm], xb1 = bv[17+4*mm], xb2 = bv[18+4*mm], xb3 = bv[19+4*mm];
            float ha0 = bfr(xa0), ha1 = bfr(xa1), ha2 = bfr(xa2), ha3 = bfr(xa3);
            float hb0 = bfr(xb0), hb1 = bfr(xb1), hb2 = bfr(xb2), hb3 = bfr(xb3);
            ah[mm][0] = pkbf(ha0, ha1); ah[mm][1] = pkbf(hb0, hb1);
            ah[mm][2] = pkbf(ha2, ha3); ah[mm][3] = pkbf(hb2, hb3);
            al[mm][0] = pkbf(xa0-ha0, xa1-ha1); al[mm][1] = pkbf(xb0-hb0, xb1-hb1);
            al[mm][2] = pkbf(xa2-ha2, xa3-ha3); al[mm][3] = pkbf(xb2-hb2, xb3-hb3);
        }

        // ---- 9-output GEMV via mma (both columns at once, paired B) ----
        float g0 = 0.f, g1 = 0.f, g2 = 0.f, g3 = 0.f;
        float q0 = 0.f, q1 = 0.f, q2 = 0.f, q3 = 0.f;
        #pragma unroll
        for (int mm = 0; mm < 4; mm++) {
            uint2 qh = s_W9ph[mm*80 + bof9];
            uint2 ql = s_W9pl[mm*80 + bof9];
            mma_full(g0,g1,g2,g3, ah[mm][0],ah[mm][1],ah[mm][2],ah[mm][3], qh.x,qh.y);
            mma_full(g0,g1,g2,g3, al[mm][0],al[mm][1],al[mm][2],al[mm][3], qh.x,qh.y);
            mma_full(g0,g1,g2,g3, ah[mm][0],ah[mm][1],ah[mm][2],ah[mm][3], ql.x,ql.y);
        }
        #pragma unroll
        for (int mm = 0; mm < 4; mm++) {
            uint2 qh = s_W9ph[mm*80 + 8 + bof9];
            uint2 ql = s_W9pl[mm*80 + 8 + bof9];
            mma_full(q0,q1,q2,q3, ah[mm][0],ah[mm][1],ah[mm][2],ah[mm][3], qh.x,qh.y);
            mma_full(q0,q1,q2,q3, al[mm][0],al[mm][1],al[mm][2],al[mm][3], qh.x,qh.y);
            mma_full(q0,q1,q2,q3, ah[mm][0],ah[mm][1],ah[mm][2],ah[mm][3], ql.x,ql.y);
        }
        float dA[9], dB[9];
        #pragma unroll
        for (int t = 0; t < 4; t++) {
            dA[2*t]   = __shfl_sync(0xffffffffu, g0, qb | t);
            dA[2*t+1] = __shfl_sync(0xffffffffu, g1, qb | t);
            dB[2*t]   = __shfl_sync(0xffffffffu, g2, qb | t);
            dB[2*t+1] = __shfl_sync(0xffffffffu, g3, qb | t);
        }
        dA[8] = __shfl_sync(0xffffffffu, q0, qb);
        dB[8] = __shfl_sync(0xffffffffu, q2, qb);

        // ---- softmax + coords for both columns ----
        float fxkA[3], fykA[3], wkkA[3], fxkB[3], fykB[3], wkkB[3];
        {
            float l0 = dA[6] + s_bw[0], l1 = dA[7] + s_bw[1], l2 = dA[8] + s_bw[2];
            float m  = fmaxf(l0, fmaxf(l1, l2));
            float e0 = __expf(l0 - m), e1 = __expf(l1 - m), e2 = __expf(l2 - m);
            float inv = 1.0f / (e0 + e1 + e2);
            wkkA[0] = e0*inv; wkkA[1] = e1*inv; wkkA[2] = e2*inv;
            #pragma unroll
            for (int k = 0; k < 3; k++) {
                float gx = cxA + dA[2*k]   * sc + s_bo[2*k];
                float gy = cyA + dA[2*k+1] * sc + s_bo[2*k+1];
                fxkA[k] = fmaf(gx, 160.f, 159.5f);
                fykA[k] = fmaf(gy, 48.f,  47.5f);
            }
            l0 = dB[6] + s_bw[0]; l1 = dB[7] + s_bw[1]; l2 = dB[8] + s_bw[2];
            m  = fmaxf(l0, fmaxf(l1, l2));
            e0 = __expf(l0 - m); e1 = __expf(l1 - m); e2 = __expf(l2 - m);
            inv = 1.0f / (e0 + e1 + e2);
            wkkB[0] = e0*inv; wkkB[1] = e1*inv; wkkB[2] = e2*inv;
            #pragma unroll
            for (int k = 0; k < 3; k++) {
                float gx = cxB + dB[2*k]   * sc + s_bo[2*k];
                float gy = cyB + dB[2*k+1] * sc + s_bo[2*k+1];
                fxkB[k] = fmaf(gx, 160.f, 159.5f);
                fykB[k] = fmaf(gy, 48.f,  47.5f);
            }
        }

        // ---- gather: 2 phases (col A, col B), each 2 rounds of 4 voxels ----
        int cc = lane & 7;
        float* stw = s_stage + w * 576;
        #pragma unroll
        for (int half = 0; half < 2; half++) {
            ull A[2][4];
            #pragma unroll
            for (int r = 0; r < 2; r++) {
                A[r][0] = A[r][1] = A[r][2] = A[r][3] = 0ull;
                int src = (((lane >> 3) + 4*r) << 2);
                #pragma unroll
                for (int k = 0; k < 3; k++) {
                    float fx = __shfl_sync(0xffffffffu, half ? fxkB[k] : fxkA[k], src);
                    float fy = __shfl_sync(0xffffffffu, half ? fykB[k] : fykA[k], src);
                    float wg = __shfl_sync(0xffffffffu, half ? wkkB[k] : wkkA[k], src);
                    float x0f = floorf(fx), y0f = floorf(fy);
                    int ix = (int)x0f, iy = (int)y0f;
                    float wx1 = fx - x0f, wy1 = fy - y0f;
                    float wx0 = 1.f - wx1, wy0 = 1.f - wy1;
                    gather8(ix,   iy,   wx0*wy0*wg, A[r], cc);
                    gather8(ix+1, iy,   wx1*wy0*wg, A[r], cc);
                    gather8(ix,   iy+1, wx0*wy1*wg, A[r], cc);
                    gather8(ix+1, iy+1, wx1*wy1*wg, A[r], cc);
                }
            }
            #pragma unroll
            for (int r = 0; r < 2; r++) {
                int vv = (lane >> 3) + 4*r;
                float2 lo0 = upk2(A[r][0]), lo1 = upk2(A[r][1]);
                float2 hi0 = upk2(A[r][2]), hi1 = upk2(A[r][3]);
                *(float4*)&stw[vv*72 + cc*4]      = make_float4(lo0.x, lo0.y, lo1.x, lo1.y);
                *(float4*)&stw[vv*72 + 32 + cc*4] = make_float4(hi0.x, hi0.y, hi1.x, hi1.y);
            }
            __syncwarp();
            #pragma unroll
            for (int p = 0; p < 8; p++) {
                int ep = 16*(p>>1) + 8*(p&1) + 2*c;
                float2 gf = *(const float2*)&stw[v*72 + ep];
                bv[16*half + 2*p] += gf.x; bv[16*half + 2*p+1] += gf.y;
            }
            __syncwarp();
        }

        // ---- re-pack A fragments (post-gather bv) ----
        #pragma unroll
        for (int mm = 0; mm < 4; mm++) {
            float xa0 = bv[4*mm],    xa1 = bv[4*mm+1],  xa2 = bv[4*mm+2],  xa3 = bv[4*mm+3];
            float xb0 = bv[16+4*mm], xb1 = bv[17+4*mm], xb2 = bv[18+4*mm], xb3 = bv[19+4*mm];
            float ha0 = bfr(xa0), ha1 = bfr(xa1), ha2 = bfr(xa2), ha3 = bfr(xa3);
            float hb0 = bfr(xb0), hb1 = bfr(xb1), hb2 = bfr(xb2), hb3 = bfr(xb3);
            ah[mm][0] = pkbf(ha0, ha1); ah[mm][1] = pkbf(hb0, hb1);
            ah[mm][2] = pkbf(ha2, ha3); ah[mm][3] = pkbf(hb2, hb3);
            al[mm][0] = pkbf(xa0-ha0, xa1-ha1); al[mm][1] = pkbf(xb0-hb0, xb1-hb1);
            al[mm][2] = pkbf(xa2-ha2, xa3-ha3); al[mm][3] = pkbf(xb2-hb2, xb3-hb3);
        }

        // ==== main matmul: paired B, 24 MMAs serve 16 voxels ====
        float hA[16], hB[16];
        #pragma unroll
        for (int n = 0; n < 8; n++) {
            float d0 = 0.f, d1 = 0.f, d2 = 0.f, d3 = 0.f;
            #pragma unroll
            for (int mm = 0; mm < 4; mm++) {
                uint2 qh = s_Bph[mm*272 + n*8 + bofB];
                uint2 ql = s_Bpl[mm*272 + n*8 + bofB];
                mma_full(d0,d1,d2,d3, ah[mm][0],ah[mm][1],ah[mm][2],ah[mm][3], qh.x,qh.y);
                mma_full(d0,d1,d2,d3, al[mm][0],al[mm][1],al[mm][2],al[mm][3], qh.x,qh.y);
                mma_full(d0,d1,d2,d3, ah[mm][0],ah[mm][1],ah[mm][2],ah[mm][3], ql.x,ql.y);
            }
            hA[2*n] = d0; hA[2*n+1] = d1;
            hB[2*n] = d2; hB[2*n+1] = d3;
        }

        // ---- bias + LayerNorm + residual, both columns ----
        #pragma unroll
        for (int col = 0; col < 2; col++) {
            float* hh = col ? hB : hA;
            float s1 = 0.f, s2 = 0.f;
            #pragma unroll
            for (int p = 0; p < 8; p++) {
                int ep = 16*(p>>1) + 8*(p&1) + 2*c;
                float2 b2 = *(const float2*)&s_bl[ep];
                hh[2*p] += b2.x; hh[2*p+1] += b2.y;
            }
            #pragma unroll
            for (int i = 0; i < 16; i++) { s1 += hh[i]; s2 += hh[i]*hh[i]; }
            #pragma unroll
            for (int s = 1; s <= 2; s <<= 1) {
                s1 += __shfl_xor_sync(0xffffffffu, s1, s);
                s2 += __shfl_xor_sync(0xffffffffu, s2, s);
            }
            float mu  = s1 * (1.f/64.f);
            float var = s2 * (1.f/64.f) - mu * mu;
            float rs  = rsqrtf(var + 1e-5f);
            #pragma unroll
            for (int p = 0; p < 8; p++) {
                int ep = 16*(p>>1) + 8*(p&1) + 2*c;
                float2 g2 = *(const float2*)&s_g[ep];
                float2 b2 = *(const float2*)&s_b[ep];
                bv[16*col + 2*p]   += (hh[2*p]   - mu) * rs * g2.x + b2.x;
                bv[16*col + 2*p+1] += (hh[2*p+1] - mu) * rs * g2.y + b2.y;
            }
        }
    }

    // ---- mean over z (both columns) + store ----
    #pragma unroll
    for (int i = 0; i < 32; i++) {
        float s = bv[i];
        s += __shfl_xor_sync(0xffffffffu, s, 4);
        s += __shfl_xor_sync(0xffffffffu, s, 8);
        s += __shfl_xor_sync(0xffffffffu, s, 16);
        bv[i] = s;
    }
    __syncthreads();
    float* obuf = s_stage;
    if (v == 0) {
        #pragma unroll
        for (int i = 0; i < 16; i++) {
            int e = 16*(i>>2) + 8*((i>>1)&1) + 2*c + (i&1);
            obuf[e * 16 + 2*w]     = bv[i]      * 0.125f;
            obuf[e * 16 + 2*w + 1] = bv[16 + i] * 0.125f;
        }
    }
    __syncthreads();
    for (int idx = tid; idx < 1024; idx += 256) {
        int e = idx >> 4, xi = idx & 15;
        out[(size_t)e * 16384 + y * 128 + xg * 16 + xi] = obuf[idx];
    }
}

extern "C" void kernel_launch(void* const* d_in, const int* in_sizes, int n_in,
                              void* d_out, int out_size) {
    const float* velo = (const float*)d_in[0];
    const float* intr = (const float*)d_in[1];
    const float* img  = (const float*)d_in[2];
    const float* bev  = (const float*)d_in[3];
    const float* Woff = (const float*)d_in[4];
    const float* boff = (const float*)d_in[5];
    const float* soff = (const float*)d_in[6];
    const float* Ww   = (const float*)d_in[7];
    const float* bw   = (const float*)d_in[8];
    const float* Wl   = (const float*)d_in[9];
    const float* bl   = (const float*)d_in[10];
    const float* lng  = (const float*)d_in[11];
    const float* lnb  = (const float*)d_in[12];

    prologue_kernel<<<963, 256>>>(img, Wl, Woff, Ww);
    bev_kernel<<<1024, 256>>>(velo, intr, bev, boff, soff,
                              bw, bl, lng, lnb, (float*)d_out);
}